// round 6
// baseline (speedup 1.0000x reference)
#include <cuda_runtime.h>
#include <cuda_bf16.h>

// FrozenBNBStableEmbedding fused gather+dequant+LayerNorm.
// R6: 2 warps per token, LN affine params in REGISTERS (was 64 L1-wavefronts
// of LDS.128 per token — the largest L1 term). One double-buffered CTA
// barrier per iteration; weight loads for next iteration prefetched.

#define D     1024
#define REP   16          // code-table replication
#define ITERS 4           // tokens per warp-pair
#define EPS   1e-5f

__global__ __launch_bounds__(256) void emb_ln_kernel(
    const int*   __restrict__ x,
    const int*   __restrict__ w,
    const float* __restrict__ absmax,
    const float* __restrict__ code,
    const float* __restrict__ lnw,
    const float* __restrict__ lnb,
    float*       __restrict__ out,
    int n_tokens)
{
    __shared__ float s_code[256 * REP];   // s_code[idx*REP + slot]
    __shared__ float s_part[2][4][4];     // [buf][pair][{sum0,sq0,sum1,sq1}]

    const int tid  = threadIdx.x;
    const int warp = tid >> 5;
    const int lane = tid & 31;
    const int pair = warp >> 1;           // 0..3
    const int half = warp & 1;            // which 512-elem half of the row

    // Fill replicated code table
    {
        const float c = code[tid];
        float4 cv = make_float4(c, c, c, c);
        float4* dst = reinterpret_cast<float4*>(&s_code[tid * REP]);
        dst[0] = cv; dst[1] = cv; dst[2] = cv; dst[3] = cv;
    }

    // LN params -> persistent registers (8 float4 per lane)
    float4 gw[4], gb[4];
    #pragma unroll
    for (int i = 0; i < 4; ++i) {
        const int f = half * 128 + i * 32 + lane;   // float4 index in row
        gw[i] = __ldg(&reinterpret_cast<const float4*>(lnw)[f]);
        gb[i] = __ldg(&reinterpret_cast<const float4*>(lnb)[f]);
    }
    __syncthreads();

    const float* tab = &s_code[lane & (REP - 1)];
    const int tok0 = blockIdx.x * (4 * ITERS) + pair;

    // Prefetch iteration 0
    int   row   = __ldg(&x[tok0]);
    float scale = __ldg(&absmax[row >> 2]);
    int4 q[4];
    {
        const int4* wrow = reinterpret_cast<const int4*>(w + (long long)row * D);
        #pragma unroll
        for (int i = 0; i < 4; ++i)
            q[i] = __ldg(&wrow[half * 128 + i * 32 + lane]);
    }

    #pragma unroll
    for (int j = 0; j < ITERS; ++j) {
        const int tok = tok0 + j * 4;

        // Dequant + local accumulation
        float v[16];
        float sum = 0.0f, sq = 0.0f;
        #pragma unroll
        for (int i = 0; i < 4; ++i) {
            float a = tab[(q[i].x & 255) * REP] * scale;
            float b = tab[(q[i].y & 255) * REP] * scale;
            float c = tab[(q[i].z & 255) * REP] * scale;
            float d = tab[(q[i].w & 255) * REP] * scale;
            v[i*4+0] = a; v[i*4+1] = b; v[i*4+2] = c; v[i*4+3] = d;
            sum += a + b + c + d;
            sq  += a*a + b*b + c*c + d*d;
        }

        // Prefetch next iteration's weights before the barrier
        int4  qn[4];
        float scn = 0.0f;
        if (j + 1 < ITERS) {
            const int rn = __ldg(&x[tok0 + (j + 1) * 4]);
            scn = __ldg(&absmax[rn >> 2]);
            const int4* wrn = reinterpret_cast<const int4*>(w + (long long)rn * D);
            #pragma unroll
            for (int i = 0; i < 4; ++i)
                qn[i] = __ldg(&wrn[half * 128 + i * 32 + lane]);
        }

        // Warp butterfly -> per-warp partial
        #pragma unroll
        for (int off = 16; off > 0; off >>= 1) {
            sum += __shfl_xor_sync(0xFFFFFFFFu, sum, off);
            sq  += __shfl_xor_sync(0xFFFFFFFFu, sq,  off);
        }
        const int buf = j & 1;
        if (lane == 0) {
            s_part[buf][pair][half * 2 + 0] = sum;
            s_part[buf][pair][half * 2 + 1] = sq;
        }
        __syncthreads();

        // Combine the pair's two partials (uniform broadcast LDS)
        const float4 p = *reinterpret_cast<const float4*>(&s_part[buf][pair][0]);
        const float mean = (p.x + p.z) * (1.0f / D);
        const float rstd = rsqrtf((p.y + p.w) * (1.0f / D) - mean * mean + EPS);

        // Fused affine epilogue from registers + streaming store
        float4* orow = reinterpret_cast<float4*>(out) + (long long)tok * (D / 4);
        #pragma unroll
        for (int i = 0; i < 4; ++i) {
            float4 o;
            o.x = (v[i*4+0] - mean) * rstd * gw[i].x + gb[i].x;
            o.y = (v[i*4+1] - mean) * rstd * gw[i].y + gb[i].y;
            o.z = (v[i*4+2] - mean) * rstd * gw[i].z + gb[i].z;
            o.w = (v[i*4+3] - mean) * rstd * gw[i].w + gb[i].w;
            __stcs(&orow[half * 128 + i * 32 + lane], o);
        }

        #pragma unroll
        for (int i = 0; i < 4; ++i) q[i] = qn[i];
        scale = scn;
    }
}

extern "C" void kernel_launch(void* const* d_in, const int* in_sizes, int n_in,
                              void* d_out, int out_size)
{
    const int*   x      = (const int*)d_in[0];
    const int*   w      = (const int*)d_in[1];
    const float* absmax = (const float*)d_in[2];
    const float* code   = (const float*)d_in[3];
    const float* lnw    = (const float*)d_in[4];
    const float* lnb    = (const float*)d_in[5];
    float*       out    = (float*)d_out;

    const int n_tokens = in_sizes[0];                 // 16384
    const int tokens_per_cta = 4 * ITERS;             // 16
    const int grid = (n_tokens + tokens_per_cta - 1) / tokens_per_cta;  // 1024
    emb_ln_kernel<<<grid, 256>>>(x, w, absmax, code, lnw, lnb, out, n_tokens);
}

// round 7
// speedup vs baseline: 1.0651x; 1.0651x over previous
#include <cuda_runtime.h>
#include <cuda_bf16.h>

// FrozenBNBStableEmbedding fused gather+dequant+LayerNorm.
// R7: warp-per-token (barrier-free, R5 structure) + LN affine params in
// persistent REGISTERS (was 64 of ~176 L1 wavefronts/token as LDS.128).
// __launch_bounds__(256,2) caps regs at 128; weight loads in 2 batches of 4.

#define D    1024
#define REP  16          // code-table replication
#define TPW  2           // tokens per warp
#define EPS  1e-5f

__global__ __launch_bounds__(256, 2) void emb_ln_kernel(
    const int*   __restrict__ x,
    const int*   __restrict__ w,
    const float* __restrict__ absmax,
    const float* __restrict__ code,
    const float* __restrict__ lnw,
    const float* __restrict__ lnb,
    float*       __restrict__ out,
    int n_tokens)
{
    __shared__ float s_code[256 * REP];   // s_code[idx*REP + slot]

    const int tid  = threadIdx.x;
    const int warp = tid >> 5;
    const int lane = tid & 31;

    // Fill replicated code table (once per CTA)
    {
        const float c = code[tid];
        float4 cv = make_float4(c, c, c, c);
        float4* dst = reinterpret_cast<float4*>(&s_code[tid * REP]);
        dst[0] = cv; dst[1] = cv; dst[2] = cv; dst[3] = cv;
    }

    // LN affine params -> persistent registers (16 float4 = 64 regs),
    // reused across TPW tokens. Zero L1 traffic in the epilogue.
    float4 gw[8], gb[8];
    #pragma unroll
    for (int i = 0; i < 8; ++i) {
        gw[i] = __ldg(&reinterpret_cast<const float4*>(lnw)[i * 32 + lane]);
        gb[i] = __ldg(&reinterpret_cast<const float4*>(lnb)[i * 32 + lane]);
    }
    __syncthreads();

    const float* tab = &s_code[lane & (REP - 1)];
    const int warp_g = blockIdx.x * 8 + warp;

    #pragma unroll
    for (int t = 0; t < TPW; ++t) {
        const int tok = warp_g * TPW + t;
        if (tok >= n_tokens) break;

        const int   row   = __ldg(&x[tok]);
        const float scale = __ldg(&absmax[row >> 2]);
        const int4* wrow  = reinterpret_cast<const int4*>(w + (long long)row * D);

        float v[32];
        float sum = 0.0f, sq = 0.0f;

        // Two batches of 4 independent 16B loads (MLP=4, lower reg peak)
        #pragma unroll
        for (int h = 0; h < 2; ++h) {
            int4 q[4];
            #pragma unroll
            for (int i = 0; i < 4; ++i)
                q[i] = __ldg(&wrow[(h * 4 + i) * 32 + lane]);
            #pragma unroll
            for (int i = 0; i < 4; ++i) {
                float a = tab[(q[i].x & 255) * REP] * scale;
                float b = tab[(q[i].y & 255) * REP] * scale;
                float c = tab[(q[i].z & 255) * REP] * scale;
                float d = tab[(q[i].w & 255) * REP] * scale;
                const int o = (h * 4 + i) * 4;
                v[o+0] = a; v[o+1] = b; v[o+2] = c; v[o+3] = d;
                sum += a + b + c + d;
                sq  += a*a + b*b + c*c + d*d;
            }
        }

        // Warp butterfly reduction (total in every lane)
        #pragma unroll
        for (int off = 16; off > 0; off >>= 1) {
            sum += __shfl_xor_sync(0xFFFFFFFFu, sum, off);
            sq  += __shfl_xor_sync(0xFFFFFFFFu, sq,  off);
        }
        const float mean = sum * (1.0f / D);
        const float rstd = rsqrtf(sq * (1.0f / D) - mean * mean + EPS);

        // Epilogue entirely from registers + streaming stores
        float4* orow = reinterpret_cast<float4*>(out) + (long long)tok * (D / 4);
        #pragma unroll
        for (int i = 0; i < 8; ++i) {
            float4 o;
            o.x = (v[i*4+0] - mean) * rstd * gw[i].x + gb[i].x;
            o.y = (v[i*4+1] - mean) * rstd * gw[i].y + gb[i].y;
            o.z = (v[i*4+2] - mean) * rstd * gw[i].z + gb[i].z;
            o.w = (v[i*4+3] - mean) * rstd * gw[i].w + gb[i].w;
            __stcs(&orow[i * 32 + lane], o);
        }
    }
}

extern "C" void kernel_launch(void* const* d_in, const int* in_sizes, int n_in,
                              void* d_out, int out_size)
{
    const int*   x      = (const int*)d_in[0];
    const int*   w      = (const int*)d_in[1];
    const float* absmax = (const float*)d_in[2];
    const float* code   = (const float*)d_in[3];
    const float* lnw    = (const float*)d_in[4];
    const float* lnb    = (const float*)d_in[5];
    float*       out    = (float*)d_out;

    const int n_tokens = in_sizes[0];                     // 16384
    const int tokens_per_cta = 8 * TPW;                   // 16
    const int grid = (n_tokens + tokens_per_cta - 1) / tokens_per_cta;  // 1024
    emb_ln_kernel<<<grid, 256>>>(x, w, absmax, code, lnw, lnb, out, n_tokens);
}